// round 4
// baseline (speedup 1.0000x reference)
#include <cuda_runtime.h>
#include <math.h>

#define Bb   2
#define CIN  64
#define HIDc 128
#define C2   256
#define DDim 32
#define HHe  56
#define WWi  56
#define HW   3136
#define PP   100352   // DDim*HW

// ---------------- scratch (static device allocations; harness-legal) ----------
__device__ float g_xz [Bb*(size_t)C2*PP];   // proj_in output (2*HID=256 ch)
__device__ float g_dw [Bb*(size_t)C2*PP];   // depthwise output (x1 = ch 0..127, x2 = ch 128..255)
__device__ float g_x1c[Bb*(size_t)HIDc*PP]; // relu(conv3d(x1))
__device__ float g_pool[Bb*HIDc*DDim];      // mean_{h,w} x2
__device__ float g_gate[Bb*HIDc*DDim];      // sigmoid gates

__device__ __forceinline__ float sigmoidf_(float x) { return 1.f / (1.f + expf(-x)); }

// ---------------- K1: proj_in  out[b,o,p] = sum_c inp[b,c,p]*W_in[o,c] -------
__global__ __launch_bounds__(256)
void k_proj(const float* __restrict__ inp, const float* __restrict__ W_in) {
    extern __shared__ float sw[];                    // 256*64 floats = 64KB
    int tid = threadIdx.x;
    for (int i = tid; i < C2*CIN; i += 256) sw[i] = W_in[i];
    __syncthreads();
    int b = blockIdx.y;
    int p = blockIdx.x * 256 + tid;
    float in[CIN];
#pragma unroll
    for (int c = 0; c < CIN; c++) in[c] = inp[(b*CIN + c)*PP + p];
    float* dst = g_xz + (size_t)b*C2*PP + p;
    for (int o = 0; o < C2; o++) {
        const float4* wr = (const float4*)(sw + o*CIN);
        float acc = 0.f;
#pragma unroll
        for (int q = 0; q < CIN/4; q++) {
            float4 w = wr[q];
            acc += in[4*q]*w.x + in[4*q+1]*w.y + in[4*q+2]*w.z + in[4*q+3]*w.w;
        }
        dst[(size_t)o*PP] = acc;
    }
}

// ---------------- K2: depthwise 3x3x3 (SAME) + fused H,W mean-pool of x2 -----
__global__ __launch_bounds__(256)
void k_dw(const float* __restrict__ W_dw) {
    __shared__ float s[3*58*58];
    __shared__ float red[256];
    int bid = blockIdx.x;
    int d = bid & 31;
    int c = (bid >> 5) & 255;
    int b = bid >> 13;
    int tid = threadIdx.x;
    const float* src = g_xz + ((size_t)(b*C2 + c))*PP;
    for (int idx = tid; idx < 3*58*58; idx += 256) {
        int ww = idx % 58; int t = idx / 58;
        int hh = t % 58;   int dd = t / 58;
        int gd = d + dd - 1, gh = hh - 1, gw = ww - 1;
        float v = 0.f;
        if ((unsigned)gd < DDim && (unsigned)gh < HHe && (unsigned)gw < WWi)
            v = src[gd*HW + gh*WWi + gw];
        s[idx] = v;
    }
    __syncthreads();
    float wv[27];
#pragma unroll
    for (int t = 0; t < 27; t++) wv[t] = W_dw[c*27 + t];
    float* dst = g_dw + ((size_t)(b*C2 + c))*PP + d*HW;
    float psum = 0.f;
    for (int idx = tid; idx < HW; idx += 256) {
        int h = idx / 56, w = idx % 56;
        float acc = 0.f;
#pragma unroll
        for (int kd = 0; kd < 3; kd++)
#pragma unroll
            for (int kh = 0; kh < 3; kh++)
#pragma unroll
                for (int kw = 0; kw < 3; kw++)
                    acc += s[(kd*58 + h+kh)*58 + (w+kw)] * wv[(kd*3+kh)*3 + kw];
        dst[idx] = acc;
        psum += acc;
    }
    if (c >= HIDc) {
        red[tid] = psum;
        __syncthreads();
        for (int off = 128; off > 0; off >>= 1) {
            if (tid < off) red[tid] += red[tid + off];
            __syncthreads();
        }
        if (tid == 0) g_pool[(b*HIDc + (c - HIDc))*DDim + d] = red[0] * (1.f/HW);
    }
}

// ---------------- K3: entire temporal branch (W_t1 -> Mamba -> W_t2 -> sigmoid)
// One block per batch (b=2). Scan state h[16] kept in registers (thread = d-channel).
__global__ __launch_bounds__(256)
void k_mamba(const float* __restrict__ W_t1, const float* __restrict__ W_t2,
             const float* __restrict__ in_w, const float* __restrict__ conv_w,
             const float* __restrict__ conv_b, const float* __restrict__ x_w,
             const float* __restrict__ dt_w, const float* __restrict__ dt_b,
             const float* __restrict__ A_log, const float* __restrict__ Dp,
             const float* __restrict__ out_w) {
    extern __shared__ float sm[];
    float* s_pool = sm;              // 128*32 = 4096
    float* s_seq  = sm + 4096;       // 32*128 = 4096   (reused as out_m)
    float* s_xr   = sm + 8192;       // 32*256 = 8192   (raw x; reused as y)
    float* s_x    = sm + 16384;      // 32*256
    float* s_z    = sm + 24576;      // 32*256
    float* s_dt   = sm + 32768;      // 32*256
    float* s_proj = sm + 40960;      // 32*40 = 1280
    int b = blockIdx.x, tid = threadIdx.x;

    for (int i = tid; i < HIDc*DDim; i += 256) s_pool[i] = g_pool[b*HIDc*DDim + i];
    __syncthreads();
    // seq[t][i] = sum_c W_t1[i][c] * pool[c][t]
    for (int idx = tid; idx < DDim*HIDc; idx += 256) {
        int t = idx >> 7, i = idx & 127;
        float a = 0.f;
        const float* w = W_t1 + i*HIDc;
        for (int c = 0; c < HIDc; c++) a += w[c] * s_pool[c*DDim + t];
        s_seq[t*HIDc + i] = a;
    }
    __syncthreads();
    // xz = seq @ in_w^T  (512 outputs: x raw / z)
    for (int idx = tid; idx < DDim*512; idx += 256) {
        int t = idx >> 9, j = idx & 511;
        float a = 0.f;
        const float* w = in_w + j*HIDc;
        const float* u = s_seq + t*HIDc;
        for (int i = 0; i < HIDc; i++) a += u[i]*w[i];
        if (j < 256) s_xr[t*256 + j] = a; else s_z[t*256 + (j-256)] = a;
    }
    __syncthreads();
    // causal depthwise conv1d (k=4) + silu
    for (int idx = tid; idx < DDim*256; idx += 256) {
        int t = idx >> 8, j = idx & 255;
        float a = conv_b[j];
#pragma unroll
        for (int k = 0; k < 4; k++) {
            int tt = t + k - 3;
            if (tt >= 0) a += s_xr[tt*256 + j] * conv_w[j*4 + k];
        }
        s_x[idx] = a * sigmoidf_(a);
    }
    __syncthreads();
    // x_proj -> (dt_raw | B | C)  (40 per step)
    for (int idx = tid; idx < DDim*40; idx += 256) {
        int t = idx / 40, q = idx % 40;
        float a = 0.f;
        const float* w = x_w + q*256;
        const float* u = s_x + t*256;
        for (int j = 0; j < 256; j++) a += u[j]*w[j];
        s_proj[idx] = a;
    }
    __syncthreads();
    // dt = softplus(dt_raw @ dt_w^T + b)
    for (int idx = tid; idx < DDim*256; idx += 256) {
        int t = idx >> 8, j = idx & 255;
        float a = dt_b[j];
#pragma unroll
        for (int r = 0; r < 8; r++) a += s_proj[t*40 + r]*dt_w[j*8 + r];
        s_dt[idx] = (a > 20.f) ? a : log1pf(expf(a));
    }
    __syncthreads();
    // selective scan: thread tid owns channel d, state in registers
    {
        int dch = tid;
        float A[16], h[16];
#pragma unroll
        for (int n = 0; n < 16; n++) { A[n] = -expf(A_log[dch*16 + n]); h[n] = 0.f; }
        float Dv = Dp[dch];
        for (int t = 0; t < DDim; t++) {
            float dtv = s_dt[t*256 + dch];
            float xv  = s_x [t*256 + dch];
            float y = 0.f;
#pragma unroll
            for (int n = 0; n < 16; n++) {
                float dA = expf(dtv * A[n]);
                h[n] = dA*h[n] + dtv * s_proj[t*40 + 8 + n] * xv;
                y += h[n] * s_proj[t*40 + 24 + n];
            }
            y += xv * Dv;
            float zv = s_z[t*256 + dch];
            y *= zv * sigmoidf_(zv);
            s_xr[t*256 + dch] = y;              // reuse s_xr as y
        }
    }
    __syncthreads();
    // out_m = y @ out_w^T  (128)
    for (int idx = tid; idx < DDim*HIDc; idx += 256) {
        int t = idx >> 7, o = idx & 127;
        float a = 0.f;
        const float* w = out_w + o*256;
        const float* u = s_xr + t*256;
        for (int j = 0; j < 256; j++) a += u[j]*w[j];
        s_seq[idx] = a;                         // reuse s_seq as out_m
    }
    __syncthreads();
    // gate = sigmoid(W_t2 @ out_m)
    for (int idx = tid; idx < DDim*HIDc; idx += 256) {
        int t = idx >> 7, o = idx & 127;
        float a = 0.f;
        const float* w = W_t2 + o*HIDc;
        const float* u = s_seq + t*HIDc;
        for (int c = 0; c < HIDc; c++) a += u[c]*w[c];
        g_gate[(b*HIDc + o)*DDim + t] = sigmoidf_(a);
    }
}

// ---------------- K4: dense 3x3x3 conv 128->128 + ReLU (the hot kernel) ------
// Block: (b, d, 4-row h-tile, 32-out-channel chunk). 256 thr = 8 o-groups x 32 pos-groups.
// Thread: 4 out-ch x 7 w-positions = 28 accums. smem: input (pad 72 -> conflict-free
// across hrow lanes) + weights [c][tap][o] pad 36 (16B-aligned float4, warp-broadcast).
#define IST 72
#define WST 36
__global__ __launch_bounds__(256)
void k_conv(const float* __restrict__ Ws) {
    extern __shared__ float smc[];
    float* sIn = smc;                   // 8*3*6*IST = 10368 floats
    float* sW  = smc + 8*3*6*IST;       // 8*27*WST  = 7776 floats
    int bid = blockIdx.x;
    int oc = bid & 3;
    int rest = bid >> 2;
    int ht = rest % 14;
    int d  = (rest / 14) % 32;
    int b  = rest / (14*32);
    int o0 = oc*32, h0 = ht*4;
    int tid = threadIdx.x;
    int og = tid >> 5, pg = tid & 31;
    int hrow = pg >> 3, wg = pg & 7, w0 = wg*7;
    float acc[4][7];
#pragma unroll
    for (int a = 0; a < 4; a++)
#pragma unroll
        for (int i = 0; i < 7; i++) acc[a][i] = 0.f;

    const float* src = g_dw + (size_t)b*C2*PP;   // x1 = channels 0..127
    for (int cc = 0; cc < 16; cc++) {
        int c0 = cc*8;
        for (int idx = tid; idx < 8*3*6*58; idx += 256) {
            int ww = idx % 58; int t = idx / 58;
            int hh = t % 6; t /= 6;
            int dd = t % 3; int cl = t / 3;
            int gd = d + dd - 1, gh = h0 + hh - 1, gw = ww - 1;
            float v = 0.f;
            if ((unsigned)gd < DDim && (unsigned)gh < HHe && (unsigned)gw < WWi)
                v = src[(size_t)(c0+cl)*PP + gd*HW + gh*WWi + gw];
            sIn[((cl*3+dd)*6 + hh)*IST + ww] = v;
        }
        for (int idx = tid; idx < 32*8*27; idx += 256) {
            int tap = idx % 27; int t = idx / 27;
            int cl = t % 8; int ol = t / 8;
            sW[(cl*27 + tap)*WST + ol] = Ws[((size_t)(o0+ol)*HIDc + (c0+cl))*27 + tap];
        }
        __syncthreads();
#pragma unroll 1
        for (int cl = 0; cl < 8; cl++) {
#pragma unroll
            for (int kd = 0; kd < 3; kd++) {
#pragma unroll
                for (int kh = 0; kh < 3; kh++) {
                    const float* row = sIn + ((cl*3+kd)*6 + hrow + kh)*IST + w0;
                    float r[9];
#pragma unroll
                    for (int j = 0; j < 9; j++) r[j] = row[j];
                    const float* wp = sW + (cl*27 + (kd*3+kh)*3)*WST + og*4;
#pragma unroll
                    for (int kw = 0; kw < 3; kw++) {
                        float4 w = *(const float4*)(wp + kw*WST);
#pragma unroll
                        for (int i = 0; i < 7; i++) {
                            float x = r[i+kw];
                            acc[0][i] += w.x*x;
                            acc[1][i] += w.y*x;
                            acc[2][i] += w.z*x;
                            acc[3][i] += w.w*x;
                        }
                    }
                }
            }
        }
        __syncthreads();
    }
    int h = h0 + hrow;
    float* dst = g_x1c + (size_t)b*HIDc*PP + (size_t)d*HW + h*WWi + w0;
#pragma unroll
    for (int oo = 0; oo < 4; oo++) {
        int o = o0 + og*4 + oo;
#pragma unroll
        for (int i = 0; i < 7; i++)
            dst[(size_t)o*PP + i] = fmaxf(acc[oo][i], 0.f);
    }
}

// ---------------- K5: out[b,o,p] = sum_c x1c[b,c,p]*gate[b,c,d(p)]*W_out[o,c] -
__global__ __launch_bounds__(256)
void k_final(const float* __restrict__ W_out, float* __restrict__ out) {
    __shared__ float sw[HIDc*64];                 // transposed: sw[c*64+o]
    int tid = threadIdx.x;
    for (int i = tid; i < HIDc*64; i += 256) {
        int c = i >> 6, o = i & 63;
        sw[i] = W_out[o*HIDc + c];
    }
    __syncthreads();
    int b = blockIdx.y;
    int p = blockIdx.x*256 + tid;
    int d = p / HW;
    float acc[64];
#pragma unroll
    for (int o = 0; o < 64; o++) acc[o] = 0.f;
    const float* src  = g_x1c + (size_t)b*HIDc*PP + p;
    const float* gate = g_gate + b*HIDc*DDim + d;
    for (int c = 0; c < HIDc; c++) {
        float v = src[(size_t)c*PP] * gate[c*DDim];
        const float4* wr = (const float4*)(sw + c*64);
#pragma unroll
        for (int q = 0; q < 16; q++) {
            float4 w = wr[q];
            acc[4*q]   += v*w.x;
            acc[4*q+1] += v*w.y;
            acc[4*q+2] += v*w.z;
            acc[4*q+3] += v*w.w;
        }
    }
    float* dst = out + (size_t)b*64*PP + p;
#pragma unroll
    for (int o = 0; o < 64; o++) dst[(size_t)o*PP] = acc[o];
}

// ---------------- launch ------------------------------------------------------
extern "C" void kernel_launch(void* const* d_in, const int* in_sizes, int n_in,
                              void* d_out, int out_size) {
    const float* inp      = (const float*)d_in[0];
    const float* W_in     = (const float*)d_in[1];
    const float* W_dw     = (const float*)d_in[2];
    const float* W_s      = (const float*)d_in[3];
    const float* W_t1     = (const float*)d_in[4];
    const float* W_t2     = (const float*)d_in[5];
    const float* m_in_w   = (const float*)d_in[6];
    const float* m_conv_w = (const float*)d_in[7];
    const float* m_conv_b = (const float*)d_in[8];
    const float* m_x_w    = (const float*)d_in[9];
    const float* m_dt_w   = (const float*)d_in[10];
    const float* m_dt_b   = (const float*)d_in[11];
    const float* m_A_log  = (const float*)d_in[12];
    const float* m_D      = (const float*)d_in[13];
    const float* m_out_w  = (const float*)d_in[14];
    const float* W_out    = (const float*)d_in[15];
    float* out = (float*)d_out;

    cudaFuncSetAttribute(k_proj,  cudaFuncAttributeMaxDynamicSharedMemorySize, C2*CIN*4);
    cudaFuncSetAttribute(k_mamba, cudaFuncAttributeMaxDynamicSharedMemorySize, 42240*4);
    cudaFuncSetAttribute(k_conv,  cudaFuncAttributeMaxDynamicSharedMemorySize, (8*3*6*IST + 8*27*WST)*4);

    k_proj <<<dim3(PP/256, Bb), 256, C2*CIN*4>>>(inp, W_in);
    k_dw   <<<Bb*C2*DDim, 256>>>(W_dw);
    k_mamba<<<Bb, 256, 42240*4>>>(W_t1, W_t2, m_in_w, m_conv_w, m_conv_b,
                                  m_x_w, m_dt_w, m_dt_b, m_A_log, m_D, m_out_w);
    k_conv <<<Bb*DDim*14*4, 256, (8*3*6*IST + 8*27*WST)*4>>>(W_s);
    k_final<<<dim3(PP/256, Bb), 256>>>(W_out, out);
}

// round 7
// speedup vs baseline: 1.9848x; 1.9848x over previous
#include <cuda_runtime.h>
#include <math.h>
#include <stdint.h>

#define Bb   2
#define CIN  64
#define HIDc 128
#define C2   256
#define DDim 32
#define HHe  56
#define WWi  56
#define HW   3136
#define PP   100352

__device__ float g_xz [Bb*(size_t)C2*PP];
__device__ float g_dw [Bb*(size_t)C2*PP];
__device__ float g_x1c[Bb*(size_t)HIDc*PP];
__device__ float g_pool[Bb*HIDc*DDim];
__device__ float g_gate[Bb*HIDc*DDim];
__device__ __align__(16) float g_wT[27*16384];   // [kd][cc][t9][o][cl], tf32-rounded

__device__ __forceinline__ float sigmoidf_(float x){ return 1.f/(1.f+expf(-x)); }
__device__ __forceinline__ unsigned tf32r(float f){ unsigned u; asm("cvt.rna.tf32.f32 %0, %1;" : "=r"(u) : "f"(f)); return u; }
__device__ __forceinline__ unsigned s2u(const void* p){ unsigned a; asm("{ .reg .u64 t; cvta.to.shared.u64 t, %1; cvt.u32.u64 %0, t; }" : "=r"(a) : "l"(p)); return a; }
__device__ __forceinline__ void cpa4(unsigned d, const void* s){
    asm volatile("cp.async.ca.shared.global [%0], [%1], 4;" :: "r"(d), "l"(s) : "memory");
}
__device__ __forceinline__ void cpa16(unsigned d, const void* s){
    asm volatile("cp.async.cg.shared.global [%0], [%1], 16;" :: "r"(d), "l"(s) : "memory");
}
__device__ __forceinline__ void mma8(float* c, const unsigned* a, const unsigned* b){
    asm volatile("mma.sync.aligned.m16n8k8.row.col.f32.tf32.tf32.f32 "
                 "{%0,%1,%2,%3}, {%4,%5,%6,%7}, {%8,%9}, {%0,%1,%2,%3};"
                 : "+f"(c[0]), "+f"(c[1]), "+f"(c[2]), "+f"(c[3])
                 : "r"(a[0]), "r"(a[1]), "r"(a[2]), "r"(a[3]), "r"(b[0]), "r"(b[1]));
}

// ---------------- K1: proj_in ----------------
__global__ __launch_bounds__(256)
void k_proj(const float* __restrict__ inp, const float* __restrict__ W_in){
    extern __shared__ float sw[];
    int tid = threadIdx.x;
    for (int i = tid; i < C2*CIN; i += 256) sw[i] = W_in[i];
    __syncthreads();
    int b = blockIdx.y;
    int p = blockIdx.x*256 + tid;
    float in[CIN];
#pragma unroll
    for (int c = 0; c < CIN; c++) in[c] = inp[(b*CIN + c)*PP + p];
    float* dst = g_xz + (size_t)b*C2*PP + p;
    for (int o = 0; o < C2; o++){
        const float4* wr = (const float4*)(sw + o*CIN);
        float acc = 0.f;
#pragma unroll
        for (int q = 0; q < CIN/4; q++){
            float4 w = wr[q];
            acc += in[4*q]*w.x + in[4*q+1]*w.y + in[4*q+2]*w.z + in[4*q+3]*w.w;
        }
        dst[(size_t)o*PP] = acc;
    }
}

// ---------------- K2: depthwise 3x3x3 + pooled x2 ----------------
__global__ __launch_bounds__(256)
void k_dw(const float* __restrict__ W_dw){
    __shared__ float s[3*58*58];
    __shared__ float red[256];
    int bid = blockIdx.x;
    int d = bid & 31, c = (bid >> 5) & 255, b = bid >> 13;
    int tid = threadIdx.x;
    const float* src = g_xz + ((size_t)(b*C2 + c))*PP;
    for (int idx = tid; idx < 3*58*58; idx += 256){
        int ww = idx % 58; int t = idx / 58;
        int hh = t % 58;   int dd = t / 58;
        int gd = d + dd - 1, gh = hh - 1, gw = ww - 1;
        float v = 0.f;
        if ((unsigned)gd < DDim && (unsigned)gh < HHe && (unsigned)gw < WWi)
            v = src[gd*HW + gh*WWi + gw];
        s[idx] = v;
    }
    __syncthreads();
    float wv[27];
#pragma unroll
    for (int t = 0; t < 27; t++) wv[t] = W_dw[c*27 + t];
    float* dst = g_dw + ((size_t)(b*C2 + c))*PP + d*HW;
    float psum = 0.f;
    for (int idx = tid; idx < HW; idx += 256){
        int h = idx / 56, w = idx % 56;
        float acc = 0.f;
#pragma unroll
        for (int kd = 0; kd < 3; kd++)
#pragma unroll
            for (int kh = 0; kh < 3; kh++)
#pragma unroll
                for (int kw = 0; kw < 3; kw++)
                    acc += s[(kd*58 + h+kh)*58 + (w+kw)] * wv[(kd*3+kh)*3 + kw];
        dst[idx] = acc;
        psum += acc;
    }
    if (c >= HIDc){
        red[tid] = psum;
        __syncthreads();
        for (int off = 128; off > 0; off >>= 1){
            if (tid < off) red[tid] += red[tid + off];
            __syncthreads();
        }
        if (tid == 0) g_pool[(b*HIDc + (c - HIDc))*DDim + d] = red[0] * (1.f/HW);
    }
}

// ---------------- K2c: weight transform -> g_wT[kd][cc][t9][o][cl] (tf32) ----
__global__ __launch_bounds__(256)
void k_wt(const float* __restrict__ Ws){
    int i = blockIdx.x*256 + threadIdx.x;
    if (i >= 27*16384) return;
    int cl = i & 7, o = (i >> 3) & 127, q = i >> 10;
    int t9 = q % 9, kcc = q / 9, cc = kcc & 15, kd = kcc >> 4;
    g_wT[i] = __uint_as_float(tf32r(Ws[((size_t)(o*HIDc) + cc*8 + cl)*27 + kd*9 + t9]));
}

// ---------------- K3: temporal branch ----------------
__global__ __launch_bounds__(256)
void k_mamba(const float* __restrict__ W_t1, const float* __restrict__ W_t2,
             const float* __restrict__ in_w, const float* __restrict__ conv_w,
             const float* __restrict__ conv_b, const float* __restrict__ x_w,
             const float* __restrict__ dt_w, const float* __restrict__ dt_b,
             const float* __restrict__ A_log, const float* __restrict__ Dp,
             const float* __restrict__ out_w){
    extern __shared__ float sm[];
    float* s_pool = sm;
    float* s_seq  = sm + 4096;
    float* s_xr   = sm + 8192;
    float* s_x    = sm + 16384;
    float* s_z    = sm + 24576;
    float* s_dt   = sm + 32768;
    float* s_proj = sm + 40960;
    int b = blockIdx.x, tid = threadIdx.x;
    for (int i = tid; i < HIDc*DDim; i += 256) s_pool[i] = g_pool[b*HIDc*DDim + i];
    __syncthreads();
    for (int idx = tid; idx < DDim*HIDc; idx += 256){
        int t = idx >> 7, i = idx & 127;
        float a = 0.f;
        const float* w = W_t1 + i*HIDc;
        for (int c = 0; c < HIDc; c++) a += w[c] * s_pool[c*DDim + t];
        s_seq[t*HIDc + i] = a;
    }
    __syncthreads();
    for (int idx = tid; idx < DDim*512; idx += 256){
        int t = idx >> 9, j = idx & 511;
        float a = 0.f;
        const float* w = in_w + j*HIDc;
        const float* u = s_seq + t*HIDc;
        for (int i = 0; i < HIDc; i++) a += u[i]*w[i];
        if (j < 256) s_xr[t*256 + j] = a; else s_z[t*256 + (j-256)] = a;
    }
    __syncthreads();
    for (int idx = tid; idx < DDim*256; idx += 256){
        int t = idx >> 8, j = idx & 255;
        float a = conv_b[j];
#pragma unroll
        for (int k = 0; k < 4; k++){
            int tt = t + k - 3;
            if (tt >= 0) a += s_xr[tt*256 + j] * conv_w[j*4 + k];
        }
        s_x[idx] = a * sigmoidf_(a);
    }
    __syncthreads();
    for (int idx = tid; idx < DDim*40; idx += 256){
        int t = idx / 40, q = idx % 40;
        float a = 0.f;
        const float* w = x_w + q*256;
        const float* u = s_x + t*256;
        for (int j = 0; j < 256; j++) a += u[j]*w[j];
        s_proj[idx] = a;
    }
    __syncthreads();
    for (int idx = tid; idx < DDim*256; idx += 256){
        int t = idx >> 8, j = idx & 255;
        float a = dt_b[j];
#pragma unroll
        for (int r = 0; r < 8; r++) a += s_proj[t*40 + r]*dt_w[j*8 + r];
        s_dt[idx] = (a > 20.f) ? a : log1pf(expf(a));
    }
    __syncthreads();
    {
        int dch = tid;
        float A[16], h[16];
#pragma unroll
        for (int n = 0; n < 16; n++){ A[n] = -expf(A_log[dch*16 + n]); h[n] = 0.f; }
        float Dv = Dp[dch];
        for (int t = 0; t < DDim; t++){
            float dtv = s_dt[t*256 + dch];
            float xv  = s_x [t*256 + dch];
            float y = 0.f;
#pragma unroll
            for (int n = 0; n < 16; n++){
                float dA = expf(dtv * A[n]);
                h[n] = dA*h[n] + dtv * s_proj[t*40 + 8 + n] * xv;
                y += h[n] * s_proj[t*40 + 24 + n];
            }
            y += xv * Dv;
            float zv = s_z[t*256 + dch];
            y *= zv * sigmoidf_(zv);
            s_xr[t*256 + dch] = y;
        }
    }
    __syncthreads();
    for (int idx = tid; idx < DDim*HIDc; idx += 256){
        int t = idx >> 7, o = idx & 127;
        float a = 0.f;
        const float* w = out_w + o*256;
        const float* u = s_xr + t*256;
        for (int j = 0; j < 256; j++) a += u[j]*w[j];
        s_seq[idx] = a;
    }
    __syncthreads();
    for (int idx = tid; idx < DDim*HIDc; idx += 256){
        int t = idx >> 7, o = idx & 127;
        float a = 0.f;
        const float* w = W_t2 + o*HIDc;
        const float* u = s_seq + t*HIDc;
        for (int c = 0; c < HIDc; c++) a += u[c]*w[c];
        g_gate[(b*HIDc + o)*DDim + t] = sigmoidf_(a);
    }
}

// ---------------- K4: tf32 mma.sync implicit-GEMM conv 128->128 + ReLU -------
// Block = (b, d, 4 h-rows): M=128 o x N=224 pos, K = (valid kd)*16cc*9tap*8ch.
// SMEM floats: in[2][8ch*360], w[2][9216]; in slab layout [ch][6h][60w] (stride
// 360 -> B-frag LDS conflict-free), pads pre-zeroed once.
#define CSM_IN  2880
#define CSM_W   9216
#define CSM_TOT (2*CSM_IN + 2*CSM_W)   // 24192 floats = 96768 B
__global__ __launch_bounds__(256)
void k_conv_mma(){
    extern __shared__ __align__(16) float smem[];
    unsigned usb = s2u(smem);
    int tid = threadIdx.x, wid = tid >> 5, lane = tid & 31;
    int lq = lane >> 2, lr = lane & 3;
    int mw = wid >> 2, nw = wid & 3;
    int bid = blockIdx.x;
    int ht = bid % 14, d = (bid/14) & 31, b = bid / (14*32);
    int h0 = ht * 4;

    // zero both input buffers once (pads / invalid-h rows stay zero forever)
    for (int i = tid; i < 2*CSM_IN; i += 256) smem[i] = 0.f;
    __syncthreads();

    int kdlist[3]; int nk = 0;
#pragma unroll
    for (int kd = 0; kd < 3; kd++){
        int gd = d + kd - 1;
        if (0 <= gd && gd < DDim) kdlist[nk++] = kd;
    }
    int S = nk * 16;

    float acc[4][7][4];
#pragma unroll
    for (int t = 0; t < 4; t++)
#pragma unroll
        for (int nt = 0; nt < 7; nt++)
#pragma unroll
            for (int j = 0; j < 4; j++) acc[t][nt][j] = 0.f;

    // ---- stage loader (cp.async) ----
    auto stage_load = [&](int s){
        int kd = kdlist[s >> 4], cc = s & 15;
        int gd = d + kd - 1;
        const float* gin = g_dw + ((size_t)(b*C2 + cc*8))*PP + (size_t)gd*HW;
        unsigned din = usb + ((s & 1)*CSM_IN)*4;
        for (int idx = tid; idx < 2688; idx += 256){
            int ch = idx / 336, r = idx - ch*336;
            int hl = r / 56, w = r - hl*56;
            int gh = h0 - 1 + hl;
            if ((unsigned)gh < 56u)
                cpa4(din + (unsigned)(ch*360 + hl*60 + w + 1)*4,
                     gin + (size_t)ch*PP + gh*56 + w);
        }
        const float* gw = g_wT + (size_t)(kd*16 + cc)*CSM_W;
        unsigned dw_ = usb + (2*CSM_IN + (s & 1)*CSM_W)*4;
        for (int idx = tid; idx < 2304; idx += 256)
            cpa16(dw_ + idx*16, gw + idx*4);
        asm volatile("cp.async.commit_group;" ::: "memory");
    };

    stage_load(0);
    for (int s = 0; s < S; s++){
        if (s + 1 < S){
            stage_load(s + 1);
            asm volatile("cp.async.wait_group 1;" ::: "memory");
        } else {
            asm volatile("cp.async.wait_group 0;" ::: "memory");
        }
        __syncthreads();
        const float* bi = smem + (s & 1)*CSM_IN;
        const float* bw = smem + 2*CSM_IN + (s & 1)*CSM_W;
#pragma unroll
        for (int t9 = 0; t9 < 9; t9++){
            int kh = t9 / 3, kw = t9 % 3;
            // A fragments: 4 M-tiles of 16 rows
            unsigned a[4][4];
            const float* wp = bw + t9*1024 + (mw*64 + lq)*8 + lr;
#pragma unroll
            for (int t = 0; t < 4; t++){
                a[t][0] = __float_as_uint(wp[t*128]);
                a[t][1] = __float_as_uint(wp[t*128 + 64]);
                a[t][2] = __float_as_uint(wp[t*128 + 4]);
                a[t][3] = __float_as_uint(wp[t*128 + 68]);
            }
            // B fragments: 7 N-tiles (this warp's h row = h0+nw)
            unsigned bfr[7][2];
            const float* ip = bi + (nw + kh)*60 + kw + lq;
#pragma unroll
            for (int nt = 0; nt < 7; nt++){
                bfr[nt][0] = __float_as_uint(ip[lr*360 + nt*8]);
                bfr[nt][1] = __float_as_uint(ip[(lr + 4)*360 + nt*8]);
            }
#pragma unroll
            for (int t = 0; t < 4; t++)
#pragma unroll
                for (int nt = 0; nt < 7; nt++)
                    mma8(acc[t][nt], a[t], bfr[nt]);
        }
        __syncthreads();
    }

    // ---- writeout with ReLU ----
    int h = h0 + nw;
#pragma unroll
    for (int t = 0; t < 4; t++){
        int o = mw*64 + t*16 + lq;
        float* base = g_x1c + ((size_t)(b*HIDc + o))*PP + (size_t)d*HW + h*56;
#pragma unroll
        for (int nt = 0; nt < 7; nt++){
            int w = nt*8 + 2*lr;
            float2 v0, v1;
            v0.x = fmaxf(acc[t][nt][0], 0.f); v0.y = fmaxf(acc[t][nt][1], 0.f);
            v1.x = fmaxf(acc[t][nt][2], 0.f); v1.y = fmaxf(acc[t][nt][3], 0.f);
            *(float2*)(base + w) = v0;
            *(float2*)(base + (size_t)8*PP + w) = v1;
        }
    }
}

// ---------------- K5: gate + proj_out ----------------
__global__ __launch_bounds__(256)
void k_final(const float* __restrict__ W_out, float* __restrict__ out){
    __shared__ float sw[HIDc*64];
    int tid = threadIdx.x;
    for (int i = tid; i < HIDc*64; i += 256){
        int c = i >> 6, o = i & 63;
        sw[i] = W_out[o*HIDc + c];
    }
    __syncthreads();
    int b = blockIdx.y;
    int p = blockIdx.x*256 + tid;
    int d = p / HW;
    float acc[64];
#pragma unroll
    for (int o = 0; o < 64; o++) acc[o] = 0.f;
    const float* src  = g_x1c + (size_t)b*HIDc*PP + p;
    const float* gate = g_gate + b*HIDc*DDim + d;
    for (int c = 0; c < HIDc; c++){
        float v = src[(size_t)c*PP] * gate[c*DDim];
        const float4* wr = (const float4*)(sw + c*64);
#pragma unroll
        for (int q = 0; q < 16; q++){
            float4 w = wr[q];
            acc[4*q]   += v*w.x;
            acc[4*q+1] += v*w.y;
            acc[4*q+2] += v*w.z;
            acc[4*q+3] += v*w.w;
        }
    }
    float* dst = out + (size_t)b*64*PP + p;
#pragma unroll
    for (int o = 0; o < 64; o++) dst[(size_t)o*PP] = acc[o];
}

// ---------------- launch ----------------
extern "C" void kernel_launch(void* const* d_in, const int* in_sizes, int n_in,
                              void* d_out, int out_size){
    const float* inp      = (const float*)d_in[0];
    const float* W_in     = (const float*)d_in[1];
    const float* W_dw     = (const float*)d_in[2];
    const float* W_s      = (const float*)d_in[3];
    const float* W_t1     = (const float*)d_in[4];
    const float* W_t2     = (const float*)d_in[5];
    const float* m_in_w   = (const float*)d_in[6];
    const float* m_conv_w = (const float*)d_in[7];
    const float* m_conv_b = (const float*)d_in[8];
    const float* m_x_w    = (const float*)d_in[9];
    const float* m_dt_w   = (const float*)d_in[10];
    const float* m_dt_b   = (const float*)d_in[11];
    const float* m_A_log  = (const float*)d_in[12];
    const float* m_D      = (const float*)d_in[13];
    const float* m_out_w  = (const float*)d_in[14];
    const float* W_out    = (const float*)d_in[15];
    float* out = (float*)d_out;

    cudaFuncSetAttribute(k_proj,     cudaFuncAttributeMaxDynamicSharedMemorySize, C2*CIN*4);
    cudaFuncSetAttribute(k_mamba,    cudaFuncAttributeMaxDynamicSharedMemorySize, 42240*4);
    cudaFuncSetAttribute(k_conv_mma, cudaFuncAttributeMaxDynamicSharedMemorySize, CSM_TOT*4);

    k_proj    <<<dim3(PP/256, Bb), 256, C2*CIN*4>>>(inp, W_in);
    k_wt      <<<1728, 256>>>(W_s);
    k_dw      <<<Bb*C2*DDim, 256>>>(W_dw);
    k_mamba   <<<Bb, 256, 42240*4>>>(W_t1, W_t2, m_in_w, m_conv_w, m_conv_b,
                                     m_x_w, m_dt_w, m_dt_b, m_A_log, m_D, m_out_w);
    k_conv_mma<<<Bb*DDim*14, 256, CSM_TOT*4>>>();
    k_final   <<<dim3(PP/256, Bb), 256>>>(W_out, out);
}

// round 8
// speedup vs baseline: 2.1909x; 1.1038x over previous
#include <cuda_runtime.h>
#include <math.h>
#include <stdint.h>

#define Bb   2
#define CIN  64
#define HIDc 128
#define C2   256
#define DDim 32
#define HHe  56
#define WWi  56
#define HW   3136
#define PP   100352

__device__ float g_xz [Bb*(size_t)C2*PP];
__device__ __align__(16) float g_dw [Bb*(size_t)C2*PP];
__device__ float g_x1c[Bb*(size_t)HIDc*PP];
__device__ float g_pool[Bb*HIDc*DDim];
__device__ float g_gate[Bb*HIDc*DDim];
__device__ __align__(16) float g_wT[27*16384];   // [kd*16+cc][t9][mt][lane][4]  A-frag packed, tf32

__device__ __forceinline__ float sigmoidf_(float x){ return 1.f/(1.f+expf(-x)); }
__device__ __forceinline__ float tf32r(float f){ unsigned u; asm("cvt.rna.tf32.f32 %0, %1;" : "=r"(u) : "f"(f)); return __uint_as_float(u); }
__device__ __forceinline__ unsigned s2u(const void* p){ unsigned a; asm("{ .reg .u64 t; cvta.to.shared.u64 t, %1; cvt.u32.u64 %0, t; }" : "=r"(a) : "l"(p)); return a; }
__device__ __forceinline__ void bwait(unsigned a, unsigned par){
    asm volatile("{\n\t.reg .pred P;\n\tLW%=:\n\tmbarrier.try_wait.parity.acquire.cta.shared::cta.b64 P, [%0], %1, 0x989680;\n\t@P bra.uni LD%=;\n\tbra.uni LW%=;\n\tLD%=:\n\t}" :: "r"(a), "r"(par) : "memory");
}
__device__ __forceinline__ void bulkcp(unsigned dst, const void* src, unsigned bytes, unsigned mbar){
    asm volatile("cp.async.bulk.shared::cluster.global.mbarrier::complete_tx::bytes [%0], [%1], %2, [%3];"
                 :: "r"(dst), "l"(src), "r"(bytes), "r"(mbar) : "memory");
}
__device__ __forceinline__ void mma8(float* c, const unsigned* a, const unsigned* b){
    asm volatile("mma.sync.aligned.m16n8k8.row.col.f32.tf32.tf32.f32 "
                 "{%0,%1,%2,%3}, {%4,%5,%6,%7}, {%8,%9}, {%0,%1,%2,%3};"
                 : "+f"(c[0]), "+f"(c[1]), "+f"(c[2]), "+f"(c[3])
                 : "r"(a[0]), "r"(a[1]), "r"(a[2]), "r"(a[3]), "r"(b[0]), "r"(b[1]));
}

// ---------------- K1: proj_in ----------------
__global__ __launch_bounds__(256)
void k_proj(const float* __restrict__ inp, const float* __restrict__ W_in){
    extern __shared__ float sw[];
    int tid = threadIdx.x;
    for (int i = tid; i < C2*CIN; i += 256) sw[i] = W_in[i];
    __syncthreads();
    int b = blockIdx.y;
    int p = blockIdx.x*256 + tid;
    float in[CIN];
#pragma unroll
    for (int c = 0; c < CIN; c++) in[c] = inp[(b*CIN + c)*PP + p];
    float* dst = g_xz + (size_t)b*C2*PP + p;
    for (int o = 0; o < C2; o++){
        const float4* wr = (const float4*)(sw + o*CIN);
        float acc = 0.f;
#pragma unroll
        for (int q = 0; q < CIN/4; q++){
            float4 w = wr[q];
            acc += in[4*q]*w.x + in[4*q+1]*w.y + in[4*q+2]*w.z + in[4*q+3]*w.w;
        }
        dst[(size_t)o*PP] = acc;
    }
}

// ---------------- K2: depthwise 3x3x3 + pooled x2 ----------------
__global__ __launch_bounds__(256)
void k_dw(const float* __restrict__ W_dw){
    __shared__ float s[3*58*58];
    __shared__ float red[256];
    int bid = blockIdx.x;
    int d = bid & 31, c = (bid >> 5) & 255, b = bid >> 13;
    int tid = threadIdx.x;
    const float* src = g_xz + ((size_t)(b*C2 + c))*PP;
    for (int idx = tid; idx < 3*58*58; idx += 256){
        int ww = idx % 58; int t = idx / 58;
        int hh = t % 58;   int dd = t / 58;
        int gd = d + dd - 1, gh = hh - 1, gw = ww - 1;
        float v = 0.f;
        if ((unsigned)gd < DDim && (unsigned)gh < HHe && (unsigned)gw < WWi)
            v = src[gd*HW + gh*WWi + gw];
        s[idx] = v;
    }
    __syncthreads();
    float wv[27];
#pragma unroll
    for (int t = 0; t < 27; t++) wv[t] = W_dw[c*27 + t];
    float* dst = g_dw + ((size_t)(b*C2 + c))*PP + d*HW;
    float psum = 0.f;
    for (int idx = tid; idx < HW; idx += 256){
        int h = idx / 56, w = idx % 56;
        float acc = 0.f;
#pragma unroll
        for (int kd = 0; kd < 3; kd++)
#pragma unroll
            for (int kh = 0; kh < 3; kh++)
#pragma unroll
                for (int kw = 0; kw < 3; kw++)
                    acc += s[(kd*58 + h+kh)*58 + (w+kw)] * wv[(kd*3+kh)*3 + kw];
        dst[idx] = acc;
        psum += acc;
    }
    if (c >= HIDc){
        red[tid] = psum;
        __syncthreads();
        for (int off = 128; off > 0; off >>= 1){
            if (tid < off) red[tid] += red[tid + off];
            __syncthreads();
        }
        if (tid == 0) g_pool[(b*HIDc + (c - HIDc))*DDim + d] = red[0] * (1.f/HW);
    }
}

// ---------------- K2c: weight transform, A-frag packed layout ----------------
// g_wT[stage=kd*16+cc][t9][mt 0..7][lane 0..31][v 0..3]:
//   o = mt*16 + (lane>>2) + 8*(v&1),  c = cc*8 + (lane&3) + 4*(v>>1)
__global__ __launch_bounds__(256)
void k_wt(const float* __restrict__ Ws){
    int i = blockIdx.x*256 + threadIdx.x;
    if (i >= 27*16384) return;
    int stage = i / 9216, r = i % 9216;
    int kd = stage >> 4, cc = stage & 15;
    int t9 = r >> 10, q = r & 1023;
    int mt = q >> 7, lane = (q >> 2) & 31, v = q & 3;
    int o = mt*16 + (lane>>2) + 8*(v&1);
    int c = cc*8 + (lane&3) + 4*(v>>1);
    g_wT[i] = tf32r(Ws[((size_t)o*HIDc + c)*27 + kd*9 + t9]);
}

// ---------------- K3: temporal branch ----------------
__global__ __launch_bounds__(256)
void k_mamba(const float* __restrict__ W_t1, const float* __restrict__ W_t2,
             const float* __restrict__ in_w, const float* __restrict__ conv_w,
             const float* __restrict__ conv_b, const float* __restrict__ x_w,
             const float* __restrict__ dt_w, const float* __restrict__ dt_b,
             const float* __restrict__ A_log, const float* __restrict__ Dp,
             const float* __restrict__ out_w){
    extern __shared__ float sm[];
    float* s_pool = sm;
    float* s_seq  = sm + 4096;
    float* s_xr   = sm + 8192;
    float* s_x    = sm + 16384;
    float* s_z    = sm + 24576;
    float* s_dt   = sm + 32768;
    float* s_proj = sm + 40960;
    int b = blockIdx.x, tid = threadIdx.x;
    for (int i = tid; i < HIDc*DDim; i += 256) s_pool[i] = g_pool[b*HIDc*DDim + i];
    __syncthreads();
    for (int idx = tid; idx < DDim*HIDc; idx += 256){
        int t = idx >> 7, i = idx & 127;
        float a = 0.f;
        const float* w = W_t1 + i*HIDc;
        for (int c = 0; c < HIDc; c++) a += w[c] * s_pool[c*DDim + t];
        s_seq[t*HIDc + i] = a;
    }
    __syncthreads();
    for (int idx = tid; idx < DDim*512; idx += 256){
        int t = idx >> 9, j = idx & 511;
        float a = 0.f;
        const float* w = in_w + j*HIDc;
        const float* u = s_seq + t*HIDc;
        for (int i = 0; i < HIDc; i++) a += u[i]*w[i];
        if (j < 256) s_xr[t*256 + j] = a; else s_z[t*256 + (j-256)] = a;
    }
    __syncthreads();
    for (int idx = tid; idx < DDim*256; idx += 256){
        int t = idx >> 8, j = idx & 255;
        float a = conv_b[j];
#pragma unroll
        for (int k = 0; k < 4; k++){
            int tt = t + k - 3;
            if (tt >= 0) a += s_xr[tt*256 + j] * conv_w[j*4 + k];
        }
        s_x[idx] = a * sigmoidf_(a);
    }
    __syncthreads();
    for (int idx = tid; idx < DDim*40; idx += 256){
        int t = idx / 40, q = idx % 40;
        float a = 0.f;
        const float* w = x_w + q*256;
        const float* u = s_x + t*256;
        for (int j = 0; j < 256; j++) a += u[j]*w[j];
        s_proj[idx] = a;
    }
    __syncthreads();
    for (int idx = tid; idx < DDim*256; idx += 256){
        int t = idx >> 8, j = idx & 255;
        float a = dt_b[j];
#pragma unroll
        for (int r = 0; r < 8; r++) a += s_proj[t*40 + r]*dt_w[j*8 + r];
        s_dt[idx] = (a > 20.f) ? a : log1pf(expf(a));
    }
    __syncthreads();
    {
        int dch = tid;
        float A[16], h[16];
#pragma unroll
        for (int n = 0; n < 16; n++){ A[n] = -expf(A_log[dch*16 + n]); h[n] = 0.f; }
        float Dv = Dp[dch];
        for (int t = 0; t < DDim; t++){
            float dtv = s_dt[t*256 + dch];
            float xv  = s_x [t*256 + dch];
            float y = 0.f;
#pragma unroll
            for (int n = 0; n < 16; n++){
                float dA = expf(dtv * A[n]);
                h[n] = dA*h[n] + dtv * s_proj[t*40 + 8 + n] * xv;
                y += h[n] * s_proj[t*40 + 24 + n];
            }
            y += xv * Dv;
            float zv = s_z[t*256 + dch];
            y *= zv * sigmoidf_(zv);
            s_xr[t*256 + dch] = y;
        }
    }
    __syncthreads();
    for (int idx = tid; idx < DDim*HIDc; idx += 256){
        int t = idx >> 7, o = idx & 127;
        float a = 0.f;
        const float* w = out_w + o*256;
        const float* u = s_xr + t*256;
        for (int j = 0; j < 256; j++) a += u[j]*w[j];
        s_seq[idx] = a;
    }
    __syncthreads();
    for (int idx = tid; idx < DDim*HIDc; idx += 256){
        int t = idx >> 7, o = idx & 127;
        float a = 0.f;
        const float* w = W_t2 + o*HIDc;
        const float* u = s_seq + t*HIDc;
        for (int c = 0; c < HIDc; c++) a += u[c]*w[c];
        g_gate[(b*HIDc + o)*DDim + t] = sigmoidf_(a);
    }
}

// ---------------- K4: tf32 mma.sync conv, cp.async.bulk staging --------------
// Block (b, d, 4 h-rows). M=128 o, N=224 pos, K = nk*16cc*9tap*8c.
// in buf: [8ch][6h][64w] data at w+4, ch stride 392 (mod32=8 -> B LDS conflict-free)
// w buf: 9216 floats, A-frag packed (one LDS.128 per lane per (t9,t))
#define IN_BUF 3136
#define W_BUF  9216
#define CSM_TOT (2*IN_BUF + 2*W_BUF)    // 24704 floats = 98816 B
__global__ __launch_bounds__(256)
void k_conv_mma(){
    extern __shared__ __align__(16) float smem[];
    __shared__ __align__(8) unsigned long long mbars[2];
    unsigned usb = s2u(smem);
    unsigned umb = s2u(mbars);
    int tid = threadIdx.x, lane = tid & 31, wid = tid >> 5;
    int lq = lane >> 2, lr = lane & 3;
    int mw = wid >> 2, nw = wid & 3;
    int bid = blockIdx.x;
    int ht = bid % 14, d = (bid/14) & 31, b = bid / (14*32);
    int h0 = ht * 4;

    for (int i = tid; i < 2*IN_BUF; i += 256) smem[i] = 0.f;
    if (tid == 0){
        asm volatile("mbarrier.init.shared.b64 [%0], 1;" :: "r"(umb) : "memory");
        asm volatile("mbarrier.init.shared.b64 [%0], 1;" :: "r"(umb + 8) : "memory");
    }
    __syncthreads();

    int kdlist[3]; int nk = 0;
#pragma unroll
    for (int kd = 0; kd < 3; kd++){
        int gd = d + kd - 1;
        if (0 <= gd && gd < DDim) kdlist[nk++] = kd;
    }
    int S = nk * 16;
    int rows_per_ch = 6 - (ht == 0) - (ht == 13);
    unsigned tx_bytes = (unsigned)(rows_per_ch*8*224 + 36864);

    auto issue = [&](int s){
        int buf = s & 1;
        int kd = kdlist[s >> 4], cc = s & 15;
        int gd = d + kd - 1;
        if (tid == 0)
            asm volatile("mbarrier.arrive.expect_tx.shared.b64 _, [%0], %1;"
                         :: "r"(umb + buf*8), "r"(tx_bytes) : "memory");
        if (tid < 48){
            int ch = tid / 6, hl = tid % 6;
            int gh = h0 - 1 + hl;
            if ((unsigned)gh < 56u){
                const float* src = g_dw + ((size_t)(b*C2 + cc*8 + ch))*PP + (size_t)gd*HW + gh*56;
                unsigned dst = usb + (unsigned)(buf*IN_BUF + ch*392 + hl*64 + 4)*4;
                bulkcp(dst, src, 224u, umb + buf*8);
            }
        } else if (tid == 48){
            const float* src = g_wT + (size_t)(kd*16 + cc)*W_BUF;
            unsigned dst = usb + (unsigned)(2*IN_BUF + buf*W_BUF)*4;
            bulkcp(dst, src, 36864u, umb + buf*8);
        }
    };

    float acc[4][7][4];
#pragma unroll
    for (int t = 0; t < 4; t++)
#pragma unroll
        for (int nt = 0; nt < 7; nt++)
#pragma unroll
            for (int j = 0; j < 4; j++) acc[t][nt][j] = 0.f;

    issue(0);
    for (int s = 0; s < S; s++){
        if (s + 1 < S) issue(s + 1);
        bwait(umb + (s&1)*8, (unsigned)((s>>1) & 1));
        const float* bi = smem + (s&1)*IN_BUF;
        const float* bw = smem + 2*IN_BUF + (s&1)*W_BUF;
#pragma unroll
        for (int t9 = 0; t9 < 9; t9++){
            int kh = t9 / 3, kw = t9 % 3;
            uint4 A[4];
            const uint4* ap = (const uint4*)(bw + t9*1024 + mw*512) + lane;
#pragma unroll
            for (int t = 0; t < 4; t++) A[t] = ap[t*32];
            unsigned bfr[7][2];
            const float* ip = bi + (nw + kh)*64 + 3 + kw + lq;
#pragma unroll
            for (int nt = 0; nt < 7; nt++){
                bfr[nt][0] = __float_as_uint(ip[lr*392 + nt*8]);
                bfr[nt][1] = __float_as_uint(ip[(lr + 4)*392 + nt*8]);
            }
#pragma unroll
            for (int t = 0; t < 4; t++)
#pragma unroll
                for (int nt = 0; nt < 7; nt++)
                    mma8(acc[t][nt], (const unsigned*)&A[t], bfr[nt]);
        }
        __syncthreads();
    }

    int h = h0 + nw;
#pragma unroll
    for (int t = 0; t < 4; t++){
        int o = mw*64 + t*16 + lq;
        float* base = g_x1c + ((size_t)(b*HIDc + o))*PP + (size_t)d*HW + h*56;
#pragma unroll
        for (int nt = 0; nt < 7; nt++){
            int w = nt*8 + 2*lr;
            float2 v0, v1;
            v0.x = fmaxf(acc[t][nt][0], 0.f); v0.y = fmaxf(acc[t][nt][1], 0.f);
            v1.x = fmaxf(acc[t][nt][2], 0.f); v1.y = fmaxf(acc[t][nt][3], 0.f);
            *(float2*)(base + w) = v0;
            *(float2*)(base + (size_t)8*PP + w) = v1;
        }
    }
}

// ---------------- K5: gate + proj_out ----------------
__global__ __launch_bounds__(256)
void k_final(const float* __restrict__ W_out, float* __restrict__ out){
    __shared__ float sw[HIDc*64];
    int tid = threadIdx.x;
    for (int i = tid; i < HIDc*64; i += 256){
        int c = i >> 6, o = i & 63;
        sw[i] = W_out[o*HIDc + c];
    }
    __syncthreads();
    int b = blockIdx.y;
    int p = blockIdx.x*256 + tid;
    int d = p / HW;
    float acc[64];
#pragma unroll
    for (int o = 0; o < 64; o++) acc[o] = 0.f;
    const float* src  = g_x1c + (size_t)b*HIDc*PP + p;
    const float* gate = g_gate + b*HIDc*DDim + d;
    for (int c = 0; c < HIDc; c++){
        float v = src[(size_t)c*PP] * gate[c*DDim];
        const float4* wr = (const float4*)(sw + c*64);
#pragma unroll
        for (int q = 0; q < 16; q++){
            float4 w = wr[q];
            acc[4*q]   += v*w.x;
            acc[4*q+1] += v*w.y;
            acc[4*q+2] += v*w.z;
            acc[4*q+3] += v*w.w;
        }
    }
    float* dst = out + (size_t)b*64*PP + p;
#pragma unroll
    for (int o = 0; o < 64; o++) dst[(size_t)o*PP] = acc[o];
}

// ---------------- launch ----------------
extern "C" void kernel_launch(void* const* d_in, const int* in_sizes, int n_in,
                              void* d_out, int out_size){
    const float* inp      = (const float*)d_in[0];
    const float* W_in     = (const float*)d_in[1];
    const float* W_dw     = (const float*)d_in[2];
    const float* W_s      = (const float*)d_in[3];
    const float* W_t1     = (const float*)d_in[4];
    const float* W_t2     = (const float*)d_in[5];
    const float* m_in_w   = (const float*)d_in[6];
    const float* m_conv_w = (const float*)d_in[7];
    const float* m_conv_b = (const float*)d_in[8];
    const float* m_x_w    = (const float*)d_in[9];
    const float* m_dt_w   = (const float*)d_in[10];
    const float* m_dt_b   = (const float*)d_in[11];
    const float* m_A_log  = (const float*)d_in[12];
    const float* m_D      = (const float*)d_in[13];
    const float* m_out_w  = (const float*)d_in[14];
    const float* W_out    = (const float*)d_in[15];
    float* out = (float*)d_out;

    cudaFuncSetAttribute(k_proj,     cudaFuncAttributeMaxDynamicSharedMemorySize, C2*CIN*4);
    cudaFuncSetAttribute(k_mamba,    cudaFuncAttributeMaxDynamicSharedMemorySize, 42240*4);
    cudaFuncSetAttribute(k_conv_mma, cudaFuncAttributeMaxDynamicSharedMemorySize, CSM_TOT*4);

    k_proj    <<<dim3(PP/256, Bb), 256, C2*CIN*4>>>(inp, W_in);
    k_wt      <<<1728, 256>>>(W_s);
    k_dw      <<<Bb*C2*DDim, 256>>>(W_dw);
    k_mamba   <<<Bb, 256, 42240*4>>>(W_t1, W_t2, m_in_w, m_conv_w, m_conv_b,
                                     m_x_w, m_dt_w, m_dt_b, m_A_log, m_D, m_out_w);
    k_conv_mma<<<Bb*DDim*14, 256, CSM_TOT*4>>>();
    k_final   <<<dim3(PP/256, Bb), 256>>>(W_out, out);
}